// round 15
// baseline (speedup 1.0000x reference)
#include <cuda_runtime.h>
#include <math.h>

// Problem constants (fixed by the reference)
#define T_DIM 1600
#define N_DIM 32
#define C_DIM 512
#define S_DIM 200
#define L_DIM (2 * S_DIM + 1)   // 401 extended states
#define NEGF  (-1e30f)
#define PAIRS 201               // thread k owns states (2k, 2k+1); k=200 even-only
#define NTHREADS 224            // 7 warps
#define STAGES 8                // SMEM emission-row ring (power of 2)
#define PF 6                    // prefetch distance in timesteps (even; <= STAGES-2)

// per-example normalized loss scratch (static device global: no allocs allowed)
__device__ float g_per_ex[N_DIM];

__device__ __forceinline__ void cp_async16(void* smem_dst, const void* gmem_src) {
    unsigned s = (unsigned)__cvta_generic_to_shared(smem_dst);
    asm volatile("cp.async.cg.shared.global [%0], [%1], 16;\n" :: "r"(s), "l"(gmem_src));
}
__device__ __forceinline__ void cp_commit() {
    asm volatile("cp.async.commit_group;\n");
}
template <int N>
__device__ __forceinline__ void cp_wait() {
    asm volatile("cp.async.wait_group %0;\n" :: "n"(N));
}

__device__ __forceinline__ float lse2(float a, float b) {
    const float m  = fmaxf(a, b);
    const float mn = fminf(a, b);
    return m + __logf(1.0f + __expf(mn - m));
}
__device__ __forceinline__ float lse3(float a, float b, float c) {
    const float mx = fmaxf(a, b);
    const float mn = fminf(a, b);
    const float m  = fmaxf(mx, c);
    const float md = fmaxf(mn, fminf(mx, c));
    const float lo = fminf(mn, c);
    return m + __logf(1.0f + __expf(md - m) + __expf(lo - m));
}

__global__ __launch_bounds__(NTHREADS, 1)
void ctc_alpha_kernel(const float* __restrict__ log_probs,   // (T, N, C)
                      const int*   __restrict__ targets,     // (N, S)
                      const int*   __restrict__ input_lens,  // (N,)
                      const int*   __restrict__ target_lens) // (N,)
{
    // emission-row staging ring. 16B alignment mandatory for cp.async.16 (R5).
    __shared__ __align__(16) float stage[STAGES][C_DIM];
    // ping-pong ODD alphas, shifted by 1: obuf[b][k+1] = alpha[2k+1],
    // obuf[b][0] = NEG (virtual alpha[-1])
    __shared__ __align__(16) float obuf[2][PAIRS + 1];
    // ping-pong EVEN alphas (needed by lane-0 halo recompute + final readout)
    __shared__ __align__(16) float ebuf[2][PAIRS];

    const int n = blockIdx.x;
    const int k = threadIdx.x;
    const int lane = k & 31;
    const bool has_e = (k < PAIRS);        // even state 2k exists (k<=200)
    const bool has_o = (k < S_DIM);        // odd state 2k+1 exists (k<=199)
    const int kc = has_e ? k : (PAIRS - 1);
    const int inlen = input_lens[n];
    const int tlen  = target_lens[n];

    // label for odd state 2k+1 + skip permission
    int ext = 0;
    bool skip = false;
    if (has_o) {
        ext = targets[n * S_DIM + k];
        skip = (k >= 1) && (ext != targets[n * S_DIM + k - 1]);
    }
    // halo constants: lane-0 threads (k = 32,64,...,192) recompute neighbor
    // pair k-1's odd update for the second sub-step. k-1 <= 191 < S_DIM always.
    const bool halo = (lane == 0) && (k > 0) && (k <= PAIRS - 1);
    int extm1 = 0; bool skipm1 = false;
    if (halo) {
        extm1 = targets[n * S_DIM + (k - 1)];
        skipm1 = (k - 1 >= 1) && (extm1 != targets[n * S_DIM + (k - 2)]);
    }

    const int stride = N_DIM * C_DIM;                  // floats per timestep
    const float* row0 = log_probs + (size_t)n * C_DIM; // row for t=0

    // coalesced copier: 128 threads x 16B = full 2KB row
    const float* cp_src = row0 + k * 4;
    const bool   cp_on  = (k < C_DIM / 4);

    // init alpha(t=0): only s=0 and s=1 feasible
    float ae = NEGF, ao = NEGF;
    if (k == 0) {
        ae = __ldg(row0 + 0);                              // blank
        ao = (tlen >= 1) ? __ldg(row0 + ext) : NEGF;       // first label
        obuf[0][0] = NEGF; obuf[1][0] = NEGF;              // virtual alpha[-1]
    }
    if (has_o) obuf[0][k + 1] = ao;
    if (has_e) ebuf[0][k] = ae;

    // prologue: prefetch rows 1..PF, two rows per commit group (3 groups)
#pragma unroll
    for (int d = 0; d < PF; d += 2) {
        if (cp_on) {
            cp_async16(&stage[(1 + d) & (STAGES - 1)][k * 4],
                       cp_src + (size_t)(1 + d) * stride);
            cp_async16(&stage[(2 + d) & (STAGES - 1)][k * 4],
                       cp_src + (size_t)(2 + d) * stride);
        }
        cp_commit();   // all threads commit (keeps group counts aligned)
    }
    __syncthreads();

    int cur = 0;
    int t = 1;
    // double-steps: (1,2),(3,4),...,(1597,1598); tail t=1599 handled after
    for (; t + 1 < T_DIM; t += 2) {
        cp_wait<2>();      // group holding rows (t, t+1) is 3rd-newest: done
        __syncthreads();   // publishes stage rows + obuf/ebuf[cur] (t-1)

        const float* stA = stage[t & (STAGES - 1)];
        const float* stB = stage[(t + 1) & (STAGES - 1)];

        // ── step A (time t): neighbor from SMEM (published at barrier) ──
        const float am1 = obuf[cur][kc];       // alpha_odd(k-1, t-1)
        float ne = lse2(ae, am1) + stA[0];
        float no = lse3(ao, ae, skip ? am1 : NEGF) + stA[ext];
        ne = (t < inlen) ? ne : ae;
        no = (t < inlen) ? no : ao;

        // halo: lane 0 recomputes neighbor pair k-1's odd update at time t
        // (expression-identical to what thread k-1 computes)
        float no_m1 = NEGF;
        if (halo) {
            const float ao_m1 = am1;               // alpha_o(k-1, t-1)
            const float ae_m1 = ebuf[cur][k - 1];  // alpha_e(k-1, t-1)
            const float ao_m2 = obuf[cur][kc - 1]; // alpha_o(k-2, t-1)
            float v = lse3(ao_m1, ae_m1, skipm1 ? ao_m2 : NEGF) + stA[extm1];
            no_m1 = (t < inlen) ? v : ao_m1;
        }

        // ── step B (time t+1): neighbor via shuffle of step-A result ──
        const float up  = __shfl_up_sync(0xffffffffu, no, 1);
        const float am1B = (lane == 0) ? ((k == 0) ? NEGF : no_m1) : up;
        const float aeB = ne, aoB = no;
        float ne2 = lse2(aeB, am1B) + stB[0];
        float no2 = lse3(aoB, aeB, skip ? am1B : NEGF) + stB[ext];
        ne2 = (t + 1 < inlen) ? ne2 : aeB;
        no2 = (t + 1 < inlen) ? no2 : aoB;
        ae = ne2;
        ao = no2;

        const int nxt = cur ^ 1;
        if (has_o) obuf[nxt][k + 1] = ao;
        if (has_e) ebuf[nxt][k] = ae;
        cur = nxt;

        // prefetch rows t+PF, t+PF+1 (their slots were read LAST iteration,
        // strictly before the barrier we just crossed)
        if (cp_on) {
            int tp = t + PF;
            if (tp < T_DIM)
                cp_async16(&stage[tp & (STAGES - 1)][k * 4],
                           cp_src + (size_t)tp * stride);
            ++tp;
            if (tp < T_DIM)
                cp_async16(&stage[tp & (STAGES - 1)][k * 4],
                           cp_src + (size_t)tp * stride);
        }
        cp_commit();
    }

    // tail single step (t == T_DIM-1 == 1599)
    cp_wait<0>();
    __syncthreads();
    if (t < T_DIM) {
        const float* stA = stage[t & (STAGES - 1)];
        const float am1 = obuf[cur][kc];
        float ne = lse2(ae, am1) + stA[0];
        float no = lse3(ao, ae, skip ? am1 : NEGF) + stA[ext];
        ne = (t < inlen) ? ne : ae;
        no = (t < inlen) ? no : ao;
        const int nxt = cur ^ 1;
        if (has_e) { ae = ne; ebuf[nxt][k] = ne; }
        if (has_o) { ao = no; obuf[nxt][k + 1] = no; }
        cur = nxt;
    }
    __syncthreads();

    if (k == 0) {
        // a_last = alpha[2*tlen] = even of pair tlen; a_prev = alpha[2*tlen-1]
        const float al = ebuf[cur][tlen];
        const float ap = (tlen > 0) ? obuf[cur][tlen] : NEGF;
        const float m  = fmaxf(al, ap);
        float per = -(m + __logf(__expf(al - m) + __expf(ap - m)));
        per = (per < 1e29f) ? per : 0.0f;              // zero_infinity
        const float norm = sqrtf(fmaxf((float)tlen, 1.0f));  // ALPHA = 0.5
        g_per_ex[n] = per / norm;
    }
}

__global__ void ctc_reduce_kernel(float* __restrict__ out)
{
    float v = g_per_ex[threadIdx.x];     // exactly N_DIM=32 threads
#pragma unroll
    for (int o = 16; o > 0; o >>= 1)
        v += __shfl_xor_sync(0xffffffffu, v, o);
    if (threadIdx.x == 0) out[0] = v / (float)N_DIM;
}

extern "C" void kernel_launch(void* const* d_in, const int* in_sizes, int n_in,
                              void* d_out, int out_size)
{
    const float* log_probs   = (const float*)d_in[0];
    const int*   targets     = (const int*)  d_in[1];
    const int*   input_lens  = (const int*)  d_in[2];
    const int*   target_lens = (const int*)  d_in[3];

    ctc_alpha_kernel<<<N_DIM, NTHREADS>>>(log_probs, targets, input_lens, target_lens);
    ctc_reduce_kernel<<<1, 32>>>((float*)d_out);
}

// round 16
// speedup vs baseline: 1.2508x; 1.2508x over previous
#include <cuda_runtime.h>
#include <math.h>

// Problem constants (fixed by the reference)
#define T_DIM 1600
#define N_DIM 32
#define C_DIM 512
#define S_DIM 200
#define L_DIM (2 * S_DIM + 1)   // 401 extended states
#define NEGF  (-1e30f)
#define PAIRS 201               // thread k owns states (2k, 2k+1)
#define NTHREADS 224            // 7 warps
#define STAGES 8                // SMEM emission-row ring (power of 2)
#define PF 6                    // prefetch distance (rows t..t+PF-1 in flight)

// per-example normalized loss scratch (static device global: no allocs allowed)
__device__ float g_per_ex[N_DIM];

__device__ __forceinline__ void cp_async16(void* smem_dst, const void* gmem_src) {
    unsigned s = (unsigned)__cvta_generic_to_shared(smem_dst);
    asm volatile("cp.async.cg.shared.global [%0], [%1], 16;\n" :: "r"(s), "l"(gmem_src));
}
__device__ __forceinline__ void cp_commit() {
    asm volatile("cp.async.commit_group;\n");
}
template <int N>
__device__ __forceinline__ void cp_wait() {
    asm volatile("cp.async.wait_group %0;\n" :: "n"(N));
}

__device__ __forceinline__ float lse2(float a, float b) {
    const float m  = fmaxf(a, b);
    const float mn = fminf(a, b);
    return m + __logf(1.0f + __expf(mn - m));
}
__device__ __forceinline__ float lse3(float a, float b, float c) {
    const float mx = fmaxf(a, b);
    const float mn = fminf(a, b);
    const float m  = fmaxf(mx, c);
    const float md = fmaxf(mn, fminf(mx, c));
    const float lo = fminf(mn, c);
    return m + __logf(1.0f + __expf(md - m) + __expf(lo - m));
}

__global__ __launch_bounds__(NTHREADS, 1)
void ctc_alpha_kernel(const float* __restrict__ log_probs,   // (T, N, C)
                      const int*   __restrict__ targets,     // (N, S)
                      const int*   __restrict__ input_lens,  // (N,)
                      const int*   __restrict__ target_lens) // (N,)
{
    // emission-row staging ring. 16B alignment mandatory for cp.async.16 (R5).
    __shared__ __align__(16) float stage[STAGES][C_DIM];
    // warp-boundary odd alphas, ping-pong. hbuf[b][w] = alpha_odd of thread
    // (32w-1) i.e. lane 31 of warp w-1; hbuf[b][0] = NEG (virtual alpha[-1]).
    __shared__ float hbuf[2][8];
    // final readout buffers
    __shared__ float fin_e[PAIRS];       // alpha[2k]
    __shared__ float fin_o[PAIRS + 1];   // alpha[2k+1] at [k+1], [0]=NEG

    const int n = blockIdx.x;
    const int k = threadIdx.x;
    const int lane = k & 31;
    const int wid  = k >> 5;
    const bool has_e = (k < PAIRS);        // even state 2k exists
    const bool has_o = (k < S_DIM);        // odd state 2k+1 exists
    const int inlen = input_lens[n];
    const int tlen  = target_lens[n];

    // label for odd state 2k+1 + skip permission
    int ext = 0;
    bool skip = false;
    if (has_o) {
        ext = targets[n * S_DIM + k];
        skip = (k >= 1) && (ext != targets[n * S_DIM + k - 1]);
    }

    const int stride = N_DIM * C_DIM;                  // floats per timestep
    const float* row0 = log_probs + (size_t)n * C_DIM; // row for t=0

    // coalesced copier: 128 threads x 16B = full 2KB row
    const float* cp_src = row0 + k * 4;
    const bool   cp_on  = (k < C_DIM / 4);

    // init alpha(t=0): only s=0 and s=1 feasible
    float ae = NEGF, ao = NEGF;
    if (k == 0) {
        ae = __ldg(row0 + 0);                              // blank
        ao = (tlen >= 1) ? __ldg(row0 + ext) : NEGF;       // first label
        hbuf[0][0] = NEGF; hbuf[1][0] = NEGF;              // virtual alpha[-1]
        fin_o[0] = NEGF;
    }
    // publish warp-boundary odd alpha for t=0 (lane 31 -> next warp's lane 0)
    if (lane == 31 && wid < 7) { hbuf[0][wid + 1] = ao; hbuf[1][wid + 1] = NEGF; }

    // prologue: prefetch rows 1..PF, one group per row
#pragma unroll
    for (int d = 1; d <= PF; ++d) {
        if (cp_on) cp_async16(&stage[d & (STAGES - 1)][k * 4],
                              cp_src + (size_t)d * stride);
        cp_commit();   // all threads commit (keeps group counts aligned)
    }
    cp_wait<PF - 2>();     // rows 1 and 2 complete (own groups)
    __syncthreads();       // ... and visible to all threads

    // cache emissions for step t=1
    float eb = stage[1][0];
    float el = stage[1][ext];

    int cur = 0;
    for (int t = 1; t < T_DIM; ++t) {
        // critical path: BAR -> shfl -> LSE -> (6x STS) -> BAR.
        // am1 = alpha_odd(k-1, t-1): lanes 1..31 via shuffle of previous-step
        // register; lane 0 via hbuf (written by lane 31 of warp-1 last step).
        const float up = __shfl_up_sync(0xffffffffu, ao, 1);
        const float am1 = (lane == 0) ? hbuf[cur][wid] : up;

        float ne = lse2(ae, am1) + eb;
        float no = lse3(ao, ae, skip ? am1 : NEGF) + el;
        ne = (t < inlen) ? ne : ae;
        no = (t < inlen) ? no : ao;
        if (has_e) ae = ne;
        if (has_o) ao = no;

        const int nxt = cur ^ 1;
        if (lane == 31 && wid < 7) hbuf[nxt][wid + 1] = ao;
        cur = nxt;

        // off-path work: prefetch emissions for t+1 (row published at the
        // barrier above thanks to wait<PF-2>), issue cp for row t+PF
        if (t + 1 < T_DIM) {
            const float* stN = stage[(t + 1) & (STAGES - 1)];
            eb = stN[0];
            el = stN[ext];
        }
        const int tp = t + PF;
        if (tp < T_DIM && cp_on)
            cp_async16(&stage[tp & (STAGES - 1)][k * 4],
                       cp_src + (size_t)tp * stride);
        cp_commit();           // every iteration: keeps group cadence fixed
        cp_wait<PF - 2>();     // rows t+1, t+2 complete before next barrier

        __syncthreads();       // publishes hbuf[cur] + stage rows
    }

    if (has_e) fin_e[k] = ae;
    if (has_o) fin_o[k + 1] = ao;
    __syncthreads();

    if (k == 0) {
        // a_last = alpha[2*tlen]; a_prev = alpha[2*tlen-1] = fin_o[tlen]
        const float al = fin_e[tlen];
        const float ap = (tlen > 0) ? fin_o[tlen] : NEGF;
        const float m  = fmaxf(al, ap);
        float per = -(m + __logf(__expf(al - m) + __expf(ap - m)));
        per = (per < 1e29f) ? per : 0.0f;              // zero_infinity
        const float norm = sqrtf(fmaxf((float)tlen, 1.0f));  // ALPHA = 0.5
        g_per_ex[n] = per / norm;
    }
}

__global__ void ctc_reduce_kernel(float* __restrict__ out)
{
    float v = g_per_ex[threadIdx.x];     // exactly N_DIM=32 threads
#pragma unroll
    for (int o = 16; o > 0; o >>= 1)
        v += __shfl_xor_sync(0xffffffffu, v, o);
    if (threadIdx.x == 0) out[0] = v / (float)N_DIM;
}

extern "C" void kernel_launch(void* const* d_in, const int* in_sizes, int n_in,
                              void* d_out, int out_size)
{
    const float* log_probs   = (const float*)d_in[0];
    const int*   targets     = (const int*)  d_in[1];
    const int*   input_lens  = (const int*)  d_in[2];
    const int*   target_lens = (const int*)  d_in[3];

    ctc_alpha_kernel<<<N_DIM, NTHREADS>>>(log_probs, targets, input_lens, target_lens);
    ctc_reduce_kernel<<<1, 32>>>((float*)d_out);
}

// round 17
// speedup vs baseline: 1.4165x; 1.1324x over previous
#include <cuda_runtime.h>
#include <math.h>

// Problem constants (fixed by the reference)
#define T_DIM 1600
#define N_DIM 32
#define C_DIM 512
#define S_DIM 200
#define L_DIM (2 * S_DIM + 1)   // 401 extended states
#define NEGF  (-1e30f)
#define PAIRS 201               // thread k owns states (2k, 2k+1); k=200 even-only
#define NTHREADS 224            // 7 warps
#define STAGES 8                // SMEM emission-row ring (power of 2)
#define PF 6                    // prefetch distance in timesteps (<= STAGES-1)

// scratch + arrival counter for in-kernel final reduction
// (static device globals: no allocs allowed)
__device__ float g_per_ex[N_DIM];
__device__ int   g_arrive = 0;

__device__ __forceinline__ void cp_async16(void* smem_dst, const void* gmem_src) {
    unsigned s = (unsigned)__cvta_generic_to_shared(smem_dst);
    asm volatile("cp.async.cg.shared.global [%0], [%1], 16;\n" :: "r"(s), "l"(gmem_src));
}
__device__ __forceinline__ void cp_commit() {
    asm volatile("cp.async.commit_group;\n");
}
template <int N>
__device__ __forceinline__ void cp_wait() {
    asm volatile("cp.async.wait_group %0;\n" :: "n"(N));
}

__global__ __launch_bounds__(NTHREADS, 1)
void ctc_alpha_kernel(const float* __restrict__ log_probs,   // (T, N, C)
                      const int*   __restrict__ targets,     // (N, S)
                      const int*   __restrict__ input_lens,  // (N,)
                      const int*   __restrict__ target_lens, // (N,)
                      float*       __restrict__ out)         // scalar
{
    // emission-row staging ring. 16B alignment mandatory for cp.async.16 (R5).
    __shared__ __align__(16) float stage[STAGES][C_DIM];
    // ping-pong ODD-state alphas, shifted by 1: obuf[b][k+1] = alpha[2k+1],
    // obuf[b][0] = NEG (virtual alpha[-1]) so thread k reads alpha[2k-1] at [k]
    __shared__ __align__(16) float obuf[2][PAIRS + 1];
    __shared__ float ebuf[PAIRS];   // final even alphas for readout

    const int n = blockIdx.x;
    const int k = threadIdx.x;
    const bool has_e = (k < PAIRS);        // even state 2k exists (k<=200)
    const bool has_o = (k < S_DIM);        // odd state 2k+1 exists (k<=199)
    const int kc = has_e ? k : (PAIRS - 1);  // clamped SMEM index
    const int inlen = input_lens[n];
    const int tlen  = target_lens[n];

    // label for odd state 2k+1 + skip permission
    int ext = 0;
    bool skip = false;
    if (has_o) {
        ext = targets[n * S_DIM + k];
        skip = (k >= 1) && (ext != targets[n * S_DIM + k - 1]);
    }

    const int stride = N_DIM * C_DIM;                  // floats per timestep
    const float* row0 = log_probs + (size_t)n * C_DIM; // row for t=0

    // coalesced copier: 128 threads x 16B = full 2KB row
    const float* cp_src = row0 + k * 4;
    const bool   cp_on  = (k < C_DIM / 4);

    // init alpha(t=0): only s=0 and s=1 feasible
    float ae = NEGF, ao = NEGF;
    if (k == 0) {
        ae = __ldg(row0 + 0);                              // blank
        ao = (tlen >= 1) ? __ldg(row0 + ext) : NEGF;       // first label
        obuf[0][0] = NEGF; obuf[1][0] = NEGF;              // virtual alpha[-1]
    }
    if (has_o) obuf[0][k + 1] = ao;

    // prologue: prefetch rows for t = 1..PF
#pragma unroll
    for (int t = 1; t <= PF; ++t) {
        if (cp_on) cp_async16(&stage[t & (STAGES - 1)][k * 4],
                              cp_src + (size_t)t * stride);
        cp_commit();   // all threads commit (keeps group counts aligned)
    }
    __syncthreads();

    int cur = 0;
    for (int t = 1; t < T_DIM; ++t) {
        cp_wait<PF - 1>();
        __syncthreads();   // publishes stage[t] and obuf[cur]

        const float* st = stage[t & (STAGES - 1)];
        const float eb  = st[0];      // blank emission: broadcast LDS
        const float el  = st[ext];    // label emission: gather LDS
        const float am1 = obuf[cur][kc];   // alpha[2k-1] (old)

        // even state 2k: LSE2(ae, am1) + eb   (blank never skips)
        const float m1  = fmaxf(ae, am1);
        const float mn1 = fminf(ae, am1);
        float ne = m1 + __logf(1.0f + __expf(mn1 - m1)) + eb;

        // odd state 2k+1: LSE3(ao, ae, skip ? am1 : NEG) + el
        const float a2  = skip ? am1 : NEGF;
        const float mxA = fmaxf(ao, ae);
        const float mnA = fminf(ao, ae);
        const float m   = fmaxf(mxA, a2);
        const float md  = fmaxf(mnA, fminf(mxA, a2));
        const float mn  = fminf(mnA, a2);
        float no = m + __logf(1.0f + __expf(md - m) + __expf(mn - m)) + el;

        // freeze past input_len (reference semantics)
        ne = (t < inlen) ? ne : ae;
        no = (t < inlen) ? no : ao;

        const int nxt = cur ^ 1;
        if (has_e) ae = ne;
        if (has_o) { ao = no; obuf[nxt][k + 1] = no; }
        cur = nxt;

        // prefetch row for t+PF (slot last read >= 2 barriers ago: safe)
        const int tp = t + PF;
        if (tp < T_DIM && cp_on)
            cp_async16(&stage[tp & (STAGES - 1)][k * 4],
                       cp_src + (size_t)tp * stride);
        cp_commit();
    }
    __syncthreads();
    if (has_e) ebuf[k] = ae;
    __syncthreads();

    if (k == 0) {
        // a_last = alpha[2*tlen] (even, pair tlen); a_prev = alpha[2*tlen-1]
        const float al = ebuf[tlen];
        const float ap = (tlen > 0) ? obuf[cur][tlen] : NEGF;
        const float m  = fmaxf(al, ap);
        float per = -(m + __logf(__expf(al - m) + __expf(ap - m)));
        per = (per < 1e29f) ? per : 0.0f;              // zero_infinity
        const float norm = sqrtf(fmaxf((float)tlen, 1.0f));  // ALPHA = 0.5
        g_per_ex[n] = per / norm;

        // in-kernel final reduction: last-arriving block sums all examples.
        // All 32 blocks are co-resident (32 << 148 SMs) so no deadlock; the
        // serial fixed-order sum keeps the result bit-deterministic.
        __threadfence();
        const int prev = atomicAdd(&g_arrive, 1);
        if (prev == N_DIM - 1) {
            float sum = 0.0f;
#pragma unroll
            for (int i = 0; i < N_DIM; ++i) sum += g_per_ex[i];
            out[0] = sum / (float)N_DIM;
            g_arrive = 0;              // reset for next graph replay
        }
    }
}

extern "C" void kernel_launch(void* const* d_in, const int* in_sizes, int n_in,
                              void* d_out, int out_size)
{
    const float* log_probs   = (const float*)d_in[0];
    const int*   targets     = (const int*)  d_in[1];
    const int*   input_lens  = (const int*)  d_in[2];
    const int*   target_lens = (const int*)  d_in[3];

    ctc_alpha_kernel<<<N_DIM, NTHREADS>>>(log_probs, targets, input_lens,
                                          target_lens, (float*)d_out);
}